// round 5
// baseline (speedup 1.0000x reference)
#include <cuda_runtime.h>
#include <cstdint>

// ProbMask: out[b,h,u,col] = (col > m_top[b,h,u]) ? 1.0f : 0.0f  (float32 output).
// rows = B*H*U = 32768, L_K = 4096 cols per row -> 512 MB of fp32 stores.
// scores input is mathematically unused: pure store-bandwidth kernel.
//
// Round-3 evidence: rel_err == 1.0 exactly with a uint8-store kernel => output
// buffer holds 4-byte (float32) elements; stored bytes read back as ~0.
// This version stores floats. One CTA per row: 512 threads x 8 floats
// (2x float4 = 32 B per thread) = 4096 floats, fully coalesced STG.E.128.

static constexpr int L_K     = 4096;
static constexpr int THREADS = 512;            // L_K / 8

__global__ __launch_bounds__(THREADS, 4)
void probmask_kernel(const int* __restrict__ m_top, float* __restrict__ out) {
    const int row  = blockIdx.x;
    const int m    = __ldg(&m_top[row]);       // one 4B load, broadcast to 512 threads
    const int t    = threadIdx.x;
    const int col0 = t << 3;                   // first of the 8 columns this thread owns

    float4 v0, v1;
    if (col0 > m) {
        // whole 8-float chunk strictly above threshold -> all ones
        v0 = make_float4(1.f, 1.f, 1.f, 1.f);
        v1 = v0;
    } else if (col0 + 7 <= m) {
        // whole chunk at/below threshold -> all zeros
        v0 = make_float4(0.f, 0.f, 0.f, 0.f);
        v1 = v0;
    } else {
        // boundary chunk (<=1 thread per row lands here)
        v0.x = (col0 + 0 > m) ? 1.f : 0.f;
        v0.y = (col0 + 1 > m) ? 1.f : 0.f;
        v0.z = (col0 + 2 > m) ? 1.f : 0.f;
        v0.w = (col0 + 3 > m) ? 1.f : 0.f;
        v1.x = (col0 + 4 > m) ? 1.f : 0.f;
        v1.y = (col0 + 5 > m) ? 1.f : 0.f;
        v1.z = (col0 + 6 > m) ? 1.f : 0.f;
        v1.w = (col0 + 7 > m) ? 1.f : 0.f;
    }

    float4* row_out = reinterpret_cast<float4*>(out + (static_cast<size_t>(row) * L_K));
    row_out[2 * t + 0] = v0;
    row_out[2 * t + 1] = v1;
}

extern "C" void kernel_launch(void* const* d_in, const int* in_sizes, int n_in,
                              void* d_out, int out_size) {
    // out_size is an ELEMENT count: rows * L_K
    const int rows = out_size / L_K;           // 32768

    // m_top: the int32 input with exactly `rows` elements (metadata: d_in[1]).
    const int* m_top = reinterpret_cast<const int*>(d_in[1]);
    for (int i = 0; i < n_in; i++) {
        if (in_sizes[i] == rows) { m_top = reinterpret_cast<const int*>(d_in[i]); break; }
    }

    float* out = reinterpret_cast<float*>(d_out);
    probmask_kernel<<<rows, THREADS>>>(m_top, out);
}

// round 6
// speedup vs baseline: 1.5493x; 1.5493x over previous
#include <cuda_runtime.h>
#include <cstdint>

// ProbMask: out[b,h,u,col] = (col > m_top[b,h,u]) ? 1.0f : 0.0f  (float32 output).
// rows = 32768, L_K = 4096 fp32 -> 512 MB of stores. Pure write-bandwidth problem.
//
// Round-5 evidence: STG.128 kernel hit L1tex=84.8% while DRAM=48% -> the SM-side
// L1 store funnel is the bottleneck, not HBM. This version bypasses L1tex with
// TMA bulk stores: each row = zeros-prefix + ones-suffix, copied from two
// constant SMEM buffers via cp.async.bulk (UBLKCP, async proxy -> L2 direct),
// plus at most one 16 B STG patch for the mixed boundary float4 (disjoint bytes,
// so no TMA/STG ordering needed).

static constexpr int L_K          = 4096;
static constexpr int ROW_BYTES    = L_K * 4;      // 16384
static constexpr int ROW_CHUNKS   = L_K / 4;      // 1024 float4 chunks per row
static constexpr int ROWS_PER_CTA = 8;
static constexpr int THREADS      = 128;

__global__ __launch_bounds__(THREADS)
void probmask_tma_kernel(const int* __restrict__ m_top, float* __restrict__ out) {
    __shared__ __align__(16) float zbuf[L_K];     // 16 KB of 0.0f
    __shared__ __align__(16) float obuf[L_K];     // 16 KB of 1.0f

    const int t = threadIdx.x;
    #pragma unroll 4
    for (int i = t; i < L_K; i += THREADS) { zbuf[i] = 0.f; obuf[i] = 1.f; }
    __syncthreads();
    // order generic SMEM writes before async-proxy (TMA) reads
    asm volatile("fence.proxy.async.shared::cta;" ::: "memory");
    __syncthreads();

    const int row0 = blockIdx.x * ROWS_PER_CTA;

    // Boundary patch: thread r fixes the single mixed float4 of row r (if any).
    if (t < ROWS_PER_CTA) {
        const int row = row0 + t;
        const int m   = __ldg(&m_top[row]);
        const int zb  = m + 1;                    // leading zero floats, in [1, 4096]
        if (zb & 3) {                             // mixed chunk exists
            const int cb = zb >> 2;               // its float4 index
            const int c0 = cb << 2;
            float4 v;
            v.x = (c0 + 0 > m) ? 1.f : 0.f;
            v.y = (c0 + 1 > m) ? 1.f : 0.f;
            v.z = (c0 + 2 > m) ? 1.f : 0.f;
            v.w = (c0 + 3 > m) ? 1.f : 0.f;
            reinterpret_cast<float4*>(out + static_cast<size_t>(row) * L_K)[cb] = v;
        }
    }

    // One thread issues all bulk copies for this CTA's rows.
    if (t == 0) {
        const uint32_t zsrc = static_cast<uint32_t>(__cvta_generic_to_shared(zbuf));
        const uint32_t osrc = static_cast<uint32_t>(__cvta_generic_to_shared(obuf));
        #pragma unroll
        for (int r = 0; r < ROWS_PER_CTA; r++) {
            const int row     = row0 + r;
            const int m       = __ldg(&m_top[row]);
            const int zb      = m + 1;
            const int zchunks = zb >> 2;                          // full zero float4s
            const int ostart  = zchunks + ((zb & 3) ? 1 : 0);     // first all-ones float4
            const uint32_t zbytes = static_cast<uint32_t>(zchunks) * 16u;
            const uint32_t obytes = static_cast<uint32_t>(ROW_CHUNKS - ostart) * 16u;
            char* gdst = reinterpret_cast<char*>(out) + static_cast<size_t>(row) * ROW_BYTES;

            if (zbytes)
                asm volatile("cp.async.bulk.global.shared::cta.bulk_group [%0], [%1], %2;"
                             :: "l"(gdst), "r"(zsrc), "r"(zbytes) : "memory");
            if (obytes)
                asm volatile("cp.async.bulk.global.shared::cta.bulk_group [%0], [%1], %2;"
                             :: "l"(gdst + static_cast<size_t>(ostart) * 16), "r"(osrc), "r"(obytes)
                             : "memory");
        }
        asm volatile("cp.async.bulk.commit_group;" ::: "memory");
        // must not exit the CTA (freeing its SMEM) while bulk copies may still read it
        asm volatile("cp.async.bulk.wait_group 0;" ::: "memory");
    }
}

extern "C" void kernel_launch(void* const* d_in, const int* in_sizes, int n_in,
                              void* d_out, int out_size) {
    const int rows = out_size / L_K;              // 32768

    // m_top: the int32 input with exactly `rows` elements (metadata: d_in[1]).
    const int* m_top = reinterpret_cast<const int*>(d_in[1]);
    for (int i = 0; i < n_in; i++) {
        if (in_sizes[i] == rows) { m_top = reinterpret_cast<const int*>(d_in[i]); break; }
    }

    float* out = reinterpret_cast<float*>(d_out);
    probmask_tma_kernel<<<rows / ROWS_PER_CTA, THREADS>>>(m_top, out);
}